// round 12
// baseline (speedup 1.0000x reference)
#include <cuda_runtime.h>
#include <cuda_fp16.h>
#include <cstdint>

// ---------------------------------------------------------------------------
// WLSMLPLayer: h = MLP(X) [3-layer, ReLU], agg[d] = sum h[src],
// out = concat([h, agg]).
// R12: fused MLP widened to 512 threads (16 warps, warp tile 32x32) to cover
//      ldmatrix/mma latency at 1 CTA/SM. CSR edge phase unchanged.
// ---------------------------------------------------------------------------

#define MAX_N 100000
#define MAX_E 3200000
#define CHUNK 1024
#define MLP_THREADS 512

// Fused-kernel SMEM layout (halves). X aliases h2 (X dead after layer 1).
#define H1_S 264                      // 256 + 8 pad
#define H2_S 520                      // 512 + 8 pad
#define X_S  136                      // 128 + 8 pad
#define H1_OFF 0
#define H2_OFF (128 * H1_S)           // 33792
#define X_OFF  H2_OFF
#define RING_OFF (H2_OFF + 128 * H2_S)   // 100352
#define RING_H (32 * 136)             // 4352 halves per stage
#define SMEM_HALVES (RING_OFF + 2 * RING_H)   // 109056
#define FUSED_SMEM (SMEM_HALVES * 2)          // 218112 B

// Scratch (device globals: allocation-free rule)
__device__ __half g_hh[MAX_N * 128];
__device__ __half g_w1[128 * 256];
__device__ __half g_w2[256 * 512];
__device__ __half g_w3[512 * 128];
__device__ int    g_counts [MAX_N];
__device__ int    g_offsets[MAX_N + 1];
__device__ int    g_cursor [MAX_N];
__device__ int    g_perm   [MAX_E];
__device__ int    g_bsum   [128];
__device__ int    g_is64;

__device__ __forceinline__ int load_idx(const void* p, int i) {
    return g_is64 ? (int)((const long long*)p)[i] : ((const int*)p)[i];
}

// ---------------------------------------------------------------------------
// One 128x128 output tile: acc = A_smem[128, K] @ B_gmem[K, N][:, n0:n0+128]
// 16 warps, warp tile 32(M) x 32(N): wm = wid>>2 (0..3), wn = wid&3.
// B-tile = 32 rows x 128 halves = 512 x 16B chunks, exactly 1 per thread.
// ---------------------------------------------------------------------------
__device__ __forceinline__ void gemm_block(
    unsigned a_u32, int AS, const __half* __restrict__ B, int N, int n0, int KT,
    unsigned ring_u32, int tid, int wm, int wn,
    int a_r, int a_k, int b_k, int b_n, float acc[2][4][4])
{
#pragma unroll
    for (int a = 0; a < 2; a++)
#pragma unroll
        for (int b = 0; b < 4; b++)
#pragma unroll
            for (int c = 0; c < 4; c++) acc[a][b][c] = 0.f;

    __syncthreads();   // all prior SMEM writes (epilogues) complete everywhere

    const int rrow = tid >> 4;            // 0..31
    const int rcol = (tid & 15) * 8;      // halves, 16B chunks

    auto issueB = [&](int kt) {
        unsigned dst = ring_u32 + ((kt & 1) * RING_H + rrow * 136 + rcol) * 2;
        const __half* src = B + (size_t)(kt * 32 + rrow) * N + n0 + rcol;
        asm volatile("cp.async.cg.shared.global [%0], [%1], 16;"
                     :: "r"(dst), "l"(src) : "memory");
        asm volatile("cp.async.commit_group;" ::: "memory");
    };

    issueB(0);
    for (int kt = 0; kt < KT; ++kt) {
        if (kt + 1 < KT) { issueB(kt + 1); asm volatile("cp.async.wait_group 1;" ::: "memory"); }
        else             { asm volatile("cp.async.wait_group 0;" ::: "memory"); }
        __syncthreads();                    // ring stage kt visible to all

        const unsigned bs0 = ring_u32 + ((kt & 1) * RING_H) * 2;

#pragma unroll
        for (int ks = 0; ks < 2; ++ks) {
            const int k0g = kt * 32 + ks * 16;   // k offset into A row
            const int k0  = ks * 16;             // k offset into ring tile
            unsigned af[2][4], bf[4][2];
#pragma unroll
            for (int mt = 0; mt < 2; ++mt) {
                unsigned addr = a_u32 + ((wm * 32 + mt * 16 + a_r) * AS + k0g + a_k) * 2;
                asm volatile("ldmatrix.sync.aligned.m8n8.x4.shared.b16 {%0,%1,%2,%3}, [%4];"
                             : "=r"(af[mt][0]), "=r"(af[mt][1]), "=r"(af[mt][2]), "=r"(af[mt][3])
                             : "r"(addr) : "memory");
            }
#pragma unroll
            for (int np = 0; np < 2; ++np) {
                unsigned addr = bs0 + ((k0 + b_k) * 136 + wn * 32 + np * 16 + b_n) * 2;
                asm volatile("ldmatrix.sync.aligned.m8n8.x4.trans.shared.b16 {%0,%1,%2,%3}, [%4];"
                             : "=r"(bf[2 * np][0]), "=r"(bf[2 * np][1]),
                               "=r"(bf[2 * np + 1][0]), "=r"(bf[2 * np + 1][1])
                             : "r"(addr) : "memory");
            }
#pragma unroll
            for (int mt = 0; mt < 2; ++mt)
#pragma unroll
                for (int nt = 0; nt < 4; ++nt)
                    asm volatile(
                        "mma.sync.aligned.m16n8k16.row.col.f32.f16.f16.f32 "
                        "{%0,%1,%2,%3}, {%4,%5,%6,%7}, {%8,%9}, {%0,%1,%2,%3};"
                        : "+f"(acc[mt][nt][0]), "+f"(acc[mt][nt][1]),
                          "+f"(acc[mt][nt][2]), "+f"(acc[mt][nt][3])
                        : "r"(af[mt][0]), "r"(af[mt][1]), "r"(af[mt][2]), "r"(af[mt][3]),
                          "r"(bf[nt][0]), "r"(bf[nt][1]));
        }
        __syncthreads();                    // stage kt free for rewrite
    }
}

// ---------------------------------------------------------------------------
// Fused 3-layer MLP: one CTA = 128 nodes; h1/h2 stay in SMEM. 512 threads.
// ---------------------------------------------------------------------------
__global__ __launch_bounds__(MLP_THREADS, 1)
void mlp_fused(const float* __restrict__ X,
               const __half* __restrict__ w1, const float* __restrict__ b1,
               const __half* __restrict__ w2, const float* __restrict__ b2,
               const __half* __restrict__ w3, const float* __restrict__ b3,
               __half* __restrict__ hh, float* __restrict__ out, int M)
{
    extern __shared__ __align__(16) __half sh[];
    const int tid  = threadIdx.x;
    const int wid  = tid >> 5, lane = tid & 31;
    const int wm   = wid >> 2, wn = wid & 3;      // 4 x 4 warp grid
    const int gid  = lane >> 2, tig = lane & 3;
    const int bm0  = blockIdx.x * 128;

    const int a_r = (lane & 7) + ((lane >> 3) & 1) * 8;
    const int a_k = ((lane >> 4) & 1) * 8;
    const int b_k = a_r;
    const int b_n = a_k;

    const unsigned base_u32 = (unsigned)__cvta_generic_to_shared(sh);
    const unsigned x_u32    = base_u32 + X_OFF  * 2;
    const unsigned h1_u32   = base_u32 + H1_OFF * 2;
    const unsigned h2_u32   = base_u32 + H2_OFF * 2;
    const unsigned ring_u32 = base_u32 + RING_OFF * 2;

    // --- zero ALL smem (pads included) ---
    {
        uint4* p = reinterpret_cast<uint4*>(sh);
        const int nchunk = SMEM_HALVES / 8;
        for (int i = tid; i < nchunk; i += MLP_THREADS)
            p[i] = make_uint4(0u, 0u, 0u, 0u);
    }
    __syncthreads();

    // --- load X tile fp32 -> fp16 into SMEM (aliases h2 region) ---
#pragma unroll
    for (int i = 0; i < 8; i++) {
        int c   = tid + MLP_THREADS * i;    // 0..4095 float4 chunks
        int row = c >> 5, col = (c & 31) * 4;
        int r   = bm0 + row;
        float4 v = make_float4(0.f, 0.f, 0.f, 0.f);
        if (r < M) v = *reinterpret_cast<const float4*>(X + (size_t)r * 128 + col);
        __half* d = sh + X_OFF + row * X_S + col;
        *reinterpret_cast<__half2*>(d)     = __floats2half2_rn(v.x, v.y);
        *reinterpret_cast<__half2*>(d + 2) = __floats2half2_rn(v.z, v.w);
    }
    __syncthreads();

    float acc[2][4][4];

    // --- layer 1: h1 = relu(X @ W1 + b1)   [K=128, N=256] ---
    for (int n0 = 0; n0 < 256; n0 += 128) {
        gemm_block(x_u32, X_S, w1, 256, n0, 4, ring_u32,
                   tid, wm, wn, a_r, a_k, b_k, b_n, acc);
#pragma unroll
        for (int mt = 0; mt < 2; ++mt)
#pragma unroll
            for (int nt = 0; nt < 4; ++nt) {
                int c = wn * 32 + nt * 8 + 2 * tig;
                float bv0 = b1[n0 + c], bv1 = b1[n0 + c + 1];
#pragma unroll
                for (int hf = 0; hf < 2; ++hf) {
                    int r = wm * 32 + mt * 16 + gid + hf * 8;
                    float v0 = fmaxf(acc[mt][nt][hf * 2 + 0] + bv0, 0.f);
                    float v1 = fmaxf(acc[mt][nt][hf * 2 + 1] + bv1, 0.f);
                    *reinterpret_cast<__half2*>(sh + H1_OFF + r * H1_S + n0 + c) =
                        __floats2half2_rn(v0, v1);
                }
            }
        __syncthreads();
    }

    // --- layer 2: h2 = relu(h1 @ W2 + b2)  [K=256, N=512] (overwrites X) ---
    for (int n0 = 0; n0 < 512; n0 += 128) {
        gemm_block(h1_u32, H1_S, w2, 512, n0, 8, ring_u32,
                   tid, wm, wn, a_r, a_k, b_k, b_n, acc);
#pragma unroll
        for (int mt = 0; mt < 2; ++mt)
#pragma unroll
            for (int nt = 0; nt < 4; ++nt) {
                int c = wn * 32 + nt * 8 + 2 * tig;
                float bv0 = b2[n0 + c], bv1 = b2[n0 + c + 1];
#pragma unroll
                for (int hf = 0; hf < 2; ++hf) {
                    int r = wm * 32 + mt * 16 + gid + hf * 8;
                    float v0 = fmaxf(acc[mt][nt][hf * 2 + 0] + bv0, 0.f);
                    float v1 = fmaxf(acc[mt][nt][hf * 2 + 1] + bv1, 0.f);
                    *reinterpret_cast<__half2*>(sh + H2_OFF + r * H2_S + n0 + c) =
                        __floats2half2_rn(v0, v1);
                }
            }
        __syncthreads();
    }

    // --- layer 3: h = h2 @ W3 + b3         [K=512, N=128] -> gmem ---
    gemm_block(h2_u32, H2_S, w3, 128, 0, 16, ring_u32,
               tid, wm, wn, a_r, a_k, b_k, b_n, acc);
#pragma unroll
    for (int mt = 0; mt < 2; ++mt)
#pragma unroll
        for (int nt = 0; nt < 4; ++nt) {
            int c = wn * 32 + nt * 8 + 2 * tig;
            float bv0 = b3[c], bv1 = b3[c + 1];
#pragma unroll
            for (int hf = 0; hf < 2; ++hf) {
                int r  = wm * 32 + mt * 16 + gid + hf * 8;
                int gr = bm0 + r;
                if (gr < M) {
                    float v0 = acc[mt][nt][hf * 2 + 0] + bv0;
                    float v1 = acc[mt][nt][hf * 2 + 1] + bv1;
                    *reinterpret_cast<__half2*>(hh + (size_t)gr * 128 + c) =
                        __floats2half2_rn(v0, v1);
                    float* orow = out + (size_t)gr * 256;
                    orow[c    ] = v0;
                    orow[c + 1] = v1;
                }
            }
        }
}

// ---------------------------------------------------------------------------
// helpers
// ---------------------------------------------------------------------------
__global__ void f2h_kernel(const float* __restrict__ in, __half* __restrict__ out, int n) {
    int idx = (blockIdx.x * blockDim.x + threadIdx.x) * 4;
    if (idx < n) {
        float4 v = *reinterpret_cast<const float4*>(in + idx);
        __half2* o = reinterpret_cast<__half2*>(out + idx);
        o[0] = __floats2half2_rn(v.x, v.y);
        o[1] = __floats2half2_rn(v.z, v.w);
    }
}

__global__ void detect_kernel(const unsigned* __restrict__ w) {
    if (threadIdx.x == 0 && blockIdx.x == 0) {
        int ok = 1;
        for (int i = 1; i < 256; i += 2) ok &= (w[i] == 0u);
        g_is64 = ok;
    }
}

// ---------------------------------------------------------------------------
// CSR build: histogram -> chunked exclusive scan -> scatter
// ---------------------------------------------------------------------------
__global__ void hist_kernel(const void* __restrict__ dstp, int* __restrict__ counts, int E) {
    int i = blockIdx.x * blockDim.x + threadIdx.x;
    if (i >= E) return;
    atomicAdd(&counts[load_idx(dstp, i)], 1);
}

__global__ void chunk_reduce(const int* __restrict__ counts, int* __restrict__ bsum, int n) {
    __shared__ int sh[256];
    int base = blockIdx.x * CHUNK;
    int s = 0;
    for (int j = threadIdx.x; j < CHUNK; j += 256) {
        int idx = base + j;
        if (idx < n) s += counts[idx];
    }
    sh[threadIdx.x] = s;
    __syncthreads();
    for (int off = 128; off > 0; off >>= 1) {
        if (threadIdx.x < off) sh[threadIdx.x] += sh[threadIdx.x + off];
        __syncthreads();
    }
    if (threadIdx.x == 0) bsum[blockIdx.x] = sh[0];
}

__global__ void scan_partials(int* __restrict__ bsum, int nb) {
    __shared__ int sh[128];
    int t = threadIdx.x;
    int v = (t < nb) ? bsum[t] : 0;
    int orig = v;
#pragma unroll
    for (int off = 1; off < 128; off <<= 1) {
        sh[t] = v;
        __syncthreads();
        int add = (t >= off) ? sh[t - off] : 0;
        __syncthreads();
        v += add;
    }
    if (t < nb) bsum[t] = v - orig;
}

__global__ void chunk_scan(const int* __restrict__ counts, const int* __restrict__ bsum,
                           int* __restrict__ offsets, int n, int E) {
    __shared__ int sh[CHUNK];
    int t = threadIdx.x;
    int g = blockIdx.x * CHUNK + t;
    int v = (g < n) ? counts[g] : 0;
    int orig = v;
#pragma unroll
    for (int off = 1; off < CHUNK; off <<= 1) {
        sh[t] = v;
        __syncthreads();
        int add = (t >= off) ? sh[t - off] : 0;
        __syncthreads();
        v += add;
    }
    if (g < n) offsets[g] = v - orig + bsum[blockIdx.x];
    if (blockIdx.x == 0 && t == 0) offsets[n] = E;
}

__global__ void scatter_kernel(const void* __restrict__ srcp, const void* __restrict__ dstp,
                               int* __restrict__ cursor, int* __restrict__ perm, int E) {
    int i = blockIdx.x * blockDim.x + threadIdx.x;
    if (i >= E) return;
    int s = load_idx(srcp, i);
    int d = load_idx(dstp, i);
    int pos = atomicAdd(&cursor[d], 1);
    perm[pos] = s;
}

// ---------------------------------------------------------------------------
// Aggregation: one warp per dst node, fp32 register accumulation, no atomics.
// ---------------------------------------------------------------------------
__global__ void agg_kernel(const int* __restrict__ offsets, const int* __restrict__ perm,
                           const __half* __restrict__ hh, float* __restrict__ out, int M)
{
    int warp = (int)((blockIdx.x * (unsigned)blockDim.x + threadIdx.x) >> 5);
    int lane = threadIdx.x & 31;
    if (warp >= M) return;

    int e0 = offsets[warp];
    const int e1 = offsets[warp + 1];

    float a0 = 0.f, a1 = 0.f, a2 = 0.f, a3 = 0.f;

    while (e0 + 32 <= e1) {
        int idx = perm[e0 + lane];
#pragma unroll
        for (int j = 0; j < 32; ++j) {
            int s = __shfl_sync(0xffffffffu, idx, j);
            uint2 raw = *reinterpret_cast<const uint2*>(hh + (size_t)s * 128 + lane * 4);
            float2 f0 = __half22float2(*reinterpret_cast<__half2*>(&raw.x));
            float2 f1 = __half22float2(*reinterpret_cast<__half2*>(&raw.y));
            a0 += f0.x; a1 += f0.y; a2 += f1.x; a3 += f1.y;
        }
        e0 += 32;
    }
    int rem = e1 - e0;
    if (rem > 0) {
        int idx = (lane < rem) ? perm[e0 + lane] : 0;
        for (int j = 0; j < rem; ++j) {
            int s = __shfl_sync(0xffffffffu, idx, j);
            uint2 raw = *reinterpret_cast<const uint2*>(hh + (size_t)s * 128 + lane * 4);
            float2 f0 = __half22float2(*reinterpret_cast<__half2*>(&raw.x));
            float2 f1 = __half22float2(*reinterpret_cast<__half2*>(&raw.y));
            a0 += f0.x; a1 += f0.y; a2 += f1.x; a3 += f1.y;
        }
    }

    *reinterpret_cast<float4*>(out + (size_t)warp * 256 + 128 + lane * 4) =
        make_float4(a0, a1, a2, a3);
}

// ---------------------------------------------------------------------------
extern "C" void kernel_launch(void* const* d_in, const int* in_sizes, int n_in,
                              void* d_out, int out_size)
{
    const float* X   = (const float*)d_in[0];
    const void*  src = d_in[1];
    const void*  dst = d_in[2];
    const float* W1  = (const float*)d_in[3];
    const float* b1  = (const float*)d_in[4];
    const float* W2  = (const float*)d_in[5];
    const float* b2  = (const float*)d_in[6];
    const float* W3  = (const float*)d_in[7];
    const float* b3  = (const float*)d_in[8];
    float* out = (float*)d_out;

    const int N1 = in_sizes[4];          // 256
    const int N2 = in_sizes[6];          // 512
    const int N3 = in_sizes[8];          // 128
    const int K1 = in_sizes[3] / N1;     // 128
    const int M  = in_sizes[0] / K1;     // 100000
    const int E  = in_sizes[1];          // 3200000

    __half *hh, *w1, *w2, *w3;
    int *counts, *offsets, *cursor, *perm, *bsum;
    cudaGetSymbolAddress((void**)&hh, g_hh);
    cudaGetSymbolAddress((void**)&w1, g_w1);
    cudaGetSymbolAddress((void**)&w2, g_w2);
    cudaGetSymbolAddress((void**)&w3, g_w3);
    cudaGetSymbolAddress((void**)&counts,  g_counts);
    cudaGetSymbolAddress((void**)&offsets, g_offsets);
    cudaGetSymbolAddress((void**)&cursor,  g_cursor);
    cudaGetSymbolAddress((void**)&perm,    g_perm);
    cudaGetSymbolAddress((void**)&bsum,    g_bsum);

    cudaFuncSetAttribute(mlp_fused,
                         cudaFuncAttributeMaxDynamicSharedMemorySize, FUSED_SMEM);

    const int MT = (M + 127) / 128;
    const int nb = (M + CHUNK - 1) / CHUNK;
    const int EB = (E + 255) / 256;

    cudaStream_t s2;
    cudaEvent_t ev_fork, ev_w, ev_join;
    cudaStreamCreateWithFlags(&s2, cudaStreamNonBlocking);
    cudaEventCreateWithFlags(&ev_fork, cudaEventDisableTiming);
    cudaEventCreateWithFlags(&ev_w,    cudaEventDisableTiming);
    cudaEventCreateWithFlags(&ev_join, cudaEventDisableTiming);

    // fork
    cudaEventRecord(ev_fork, 0);
    cudaStreamWaitEvent(s2, ev_fork, 0);

    // side stream: weight conversions, then CSR build
    f2h_kernel<<<(K1 * N1 / 4 + 255) / 256, 256, 0, s2>>>(W1, w1, K1 * N1);
    f2h_kernel<<<(N1 * N2 / 4 + 255) / 256, 256, 0, s2>>>(W2, w2, N1 * N2);
    f2h_kernel<<<(N2 * N3 / 4 + 255) / 256, 256, 0, s2>>>(W3, w3, N2 * N3);
    cudaEventRecord(ev_w, s2);

    detect_kernel <<<1, 1, 0, s2>>>((const unsigned*)src);
    cudaMemsetAsync(counts, 0, (size_t)M * sizeof(int), s2);
    hist_kernel   <<<EB, 256, 0, s2>>>(dst, counts, E);
    chunk_reduce  <<<nb, 256, 0, s2>>>(counts, bsum, M);
    scan_partials <<<1, 128, 0, s2>>>(bsum, nb);
    chunk_scan    <<<nb, CHUNK, 0, s2>>>(counts, bsum, offsets, M, E);
    cudaMemcpyAsync(cursor, offsets, (size_t)M * sizeof(int),
                    cudaMemcpyDeviceToDevice, s2);
    scatter_kernel<<<EB, 256, 0, s2>>>(src, dst, cursor, perm, E);
    cudaEventRecord(ev_join, s2);

    // main: fused MLP (needs converted weights)
    cudaStreamWaitEvent(0, ev_w, 0);
    mlp_fused<<<MT, MLP_THREADS, FUSED_SMEM>>>(X, w1, b1, w2, b2, w3, b3, hh, out, M);

    // join: aggregation needs both the CSR and hh
    cudaStreamWaitEvent(0, ev_join, 0);
    agg_kernel<<<(M + 7) / 8, 256>>>(offsets, perm, hh, out, M);
}

// round 14
// speedup vs baseline: 1.0534x; 1.0534x over previous
#include <cuda_runtime.h>
#include <cuda_fp16.h>
#include <cstdint>

// ---------------------------------------------------------------------------
// WLSMLPLayer: h = MLP(X) [3-layer, ReLU], agg[d] = sum h[src],
// out = concat([h, agg]).
// R13: fused MLP with 3-stage B ring + ONE barrier per k-tile (halves barrier
//      count); SMEM zero-init removed (pads provably never read).
// ---------------------------------------------------------------------------

#define MAX_N 100000
#define MAX_E 3200000
#define CHUNK 1024
#define MLP_THREADS 512

// Fused-kernel SMEM layout (halves). X aliases h2 (X dead after layer 1).
#define H1_S 264                      // 256 + 8 pad
#define H2_S 520                      // 512 + 8 pad
#define X_S  136                      // 128 + 8 pad
#define H1_OFF 0
#define H2_OFF (128 * H1_S)           // 33792
#define X_OFF  H2_OFF
#define RING_OFF (H2_OFF + 128 * H2_S)   // 100352
#define RING_H (32 * 136)             // 4352 halves per stage
#define NSTAGE 3
#define SMEM_HALVES (RING_OFF + NSTAGE * RING_H)   // 113408
#define FUSED_SMEM (SMEM_HALVES * 2)               // 226816 B (< 227KB cap)

// Scratch (device globals: allocation-free rule)
__device__ __half g_hh[MAX_N * 128];
__device__ __half g_w1[128 * 256];
__device__ __half g_w2[256 * 512];
__device__ __half g_w3[512 * 128];
__device__ int    g_counts [MAX_N];
__device__ int    g_offsets[MAX_N + 1];
__device__ int    g_cursor [MAX_N];
__device__ int    g_perm   [MAX_E];
__device__ int    g_bsum   [128];
__device__ int    g_is64;

__device__ __forceinline__ int load_idx(const void* p, int i) {
    return g_is64 ? (int)((const long long*)p)[i] : ((const int*)p)[i];
}

// ---------------------------------------------------------------------------
// One 128x128 output tile: acc = A_smem[128, K] @ B_gmem[K, N][:, n0:n0+128]
// 16 warps, warp tile 32(M) x 32(N). B streamed via 3-stage cp.async ring,
// ONE __syncthreads per k-tile:
//   entry barrier proves prior compute done -> issueB(0) safe to reuse stages
//   iter kt: wait<1> (group kt landed) -> barrier (visible to all; stage kt-1
//   consumed by all) -> issueB(kt+2) (rewrites stage kt-1's slot) -> compute.
// ---------------------------------------------------------------------------
__device__ __forceinline__ void gemm_block(
    unsigned a_u32, int AS, const __half* __restrict__ B, int N, int n0, int KT,
    unsigned ring_u32, int tid, int wm, int wn,
    int a_r, int a_k, int b_k, int b_n, float acc[2][4][4])
{
#pragma unroll
    for (int a = 0; a < 2; a++)
#pragma unroll
        for (int b = 0; b < 4; b++)
#pragma unroll
            for (int c = 0; c < 4; c++) acc[a][b][c] = 0.f;

    __syncthreads();   // prior epilogue writes + prior ring reads complete

    const int rrow = tid >> 4;            // 0..31
    const int rcol = (tid & 15) * 8;      // halves, 16B chunks

    auto issueB = [&](int kt) {
        unsigned dst = ring_u32 + ((kt % NSTAGE) * RING_H + rrow * 136 + rcol) * 2;
        const __half* src = B + (size_t)(kt * 32 + rrow) * N + n0 + rcol;
        asm volatile("cp.async.cg.shared.global [%0], [%1], 16;"
                     :: "r"(dst), "l"(src) : "memory");
        asm volatile("cp.async.commit_group;" ::: "memory");
    };

    issueB(0);
    if (KT > 1) issueB(1);
    else        asm volatile("cp.async.commit_group;" ::: "memory");

    for (int kt = 0; kt < KT; ++kt) {
        asm volatile("cp.async.wait_group 1;" ::: "memory");   // group kt landed
        __syncthreads();                   // ...for all threads; stage kt-1 free
        if (kt + 2 < KT) issueB(kt + 2);   // rewrites stage (kt-1) % NSTAGE
        else             asm volatile("cp.async.commit_group;" ::: "memory");

        const unsigned bs0 = ring_u32 + ((kt % NSTAGE) * RING_H) * 2;

#pragma unroll
        for (int ks = 0; ks < 2; ++ks) {
            const int k0g = kt * 32 + ks * 16;   // k offset into A row
            const int k0  = ks * 16;             // k offset into ring tile
            unsigned af[2][4], bf[4][2];
#pragma unroll
            for (int mt = 0; mt < 2; ++mt) {
                unsigned addr = a_u32 + ((wm * 32 + mt * 16 + a_r) * AS + k0g + a_k) * 2;
                asm volatile("ldmatrix.sync.aligned.m8n8.x4.shared.b16 {%0,%1,%2,%3}, [%4];"
                             : "=r"(af[mt][0]), "=r"(af[mt][1]), "=r"(af[mt][2]), "=r"(af[mt][3])
                             : "r"(addr) : "memory");
            }
#pragma unroll
            for (int np = 0; np < 2; ++np) {
                unsigned addr = bs0 + ((k0 + b_k) * 136 + wn * 32 + np * 16 + b_n) * 2;
                asm volatile("ldmatrix.sync.aligned.m8n8.x4.trans.shared.b16 {%0,%1,%2,%3}, [%4];"
                             : "=r"(bf[2 * np][0]), "=r"(bf[2 * np][1]),
                               "=r"(bf[2 * np + 1][0]), "=r"(bf[2 * np + 1][1])
                             : "r"(addr) : "memory");
            }
#pragma unroll
            for (int mt = 0; mt < 2; ++mt)
#pragma unroll
                for (int nt = 0; nt < 4; ++nt)
                    asm volatile(
                        "mma.sync.aligned.m16n8k16.row.col.f32.f16.f16.f32 "
                        "{%0,%1,%2,%3}, {%4,%5,%6,%7}, {%8,%9}, {%0,%1,%2,%3};"
                        : "+f"(acc[mt][nt][0]), "+f"(acc[mt][nt][1]),
                          "+f"(acc[mt][nt][2]), "+f"(acc[mt][nt][3])
                        : "r"(af[mt][0]), "r"(af[mt][1]), "r"(af[mt][2]), "r"(af[mt][3]),
                          "r"(bf[nt][0]), "r"(bf[nt][1]));
        }
        // no trailing barrier: next iteration's barrier covers stage reuse
    }
}

// ---------------------------------------------------------------------------
// Fused 3-layer MLP: one CTA = 128 nodes; h1/h2 stay in SMEM. 512 threads.
// ---------------------------------------------------------------------------
__global__ __launch_bounds__(MLP_THREADS, 1)
void mlp_fused(const float* __restrict__ X,
               const __half* __restrict__ w1, const float* __restrict__ b1,
               const __half* __restrict__ w2, const float* __restrict__ b2,
               const __half* __restrict__ w3, const float* __restrict__ b3,
               __half* __restrict__ hh, float* __restrict__ out, int M)
{
    extern __shared__ __align__(16) __half sh[];
    const int tid  = threadIdx.x;
    const int wid  = tid >> 5, lane = tid & 31;
    const int wm   = wid >> 2, wn = wid & 3;      // 4 x 4 warp grid
    const int gid  = lane >> 2, tig = lane & 3;
    const int bm0  = blockIdx.x * 128;

    const int a_r = (lane & 7) + ((lane >> 3) & 1) * 8;
    const int a_k = ((lane >> 4) & 1) * 8;
    const int b_k = a_r;
    const int b_n = a_k;

    const unsigned base_u32 = (unsigned)__cvta_generic_to_shared(sh);
    const unsigned x_u32    = base_u32 + X_OFF  * 2;
    const unsigned h1_u32   = base_u32 + H1_OFF * 2;
    const unsigned h2_u32   = base_u32 + H2_OFF * 2;
    const unsigned ring_u32 = base_u32 + RING_OFF * 2;

    // --- load X tile fp32 -> fp16 into SMEM (aliases h2 region) ---
#pragma unroll
    for (int i = 0; i < 8; i++) {
        int c   = tid + MLP_THREADS * i;    // 0..4095 float4 chunks
        int row = c >> 5, col = (c & 31) * 4;
        int r   = bm0 + row;
        float4 v = make_float4(0.f, 0.f, 0.f, 0.f);
        if (r < M) v = *reinterpret_cast<const float4*>(X + (size_t)r * 128 + col);
        __half* d = sh + X_OFF + row * X_S + col;
        *reinterpret_cast<__half2*>(d)     = __floats2half2_rn(v.x, v.y);
        *reinterpret_cast<__half2*>(d + 2) = __floats2half2_rn(v.z, v.w);
    }
    // gemm_block's entry barrier orders these writes before compute

    float acc[2][4][4];

    // --- layer 1: h1 = relu(X @ W1 + b1)   [K=128, N=256] ---
    for (int n0 = 0; n0 < 256; n0 += 128) {
        gemm_block(x_u32, X_S, w1, 256, n0, 4, ring_u32,
                   tid, wm, wn, a_r, a_k, b_k, b_n, acc);
#pragma unroll
        for (int mt = 0; mt < 2; ++mt)
#pragma unroll
            for (int nt = 0; nt < 4; ++nt) {
                int c = wn * 32 + nt * 8 + 2 * tig;
                float bv0 = b1[n0 + c], bv1 = b1[n0 + c + 1];
#pragma unroll
                for (int hf = 0; hf < 2; ++hf) {
                    int r = wm * 32 + mt * 16 + gid + hf * 8;
                    float v0 = fmaxf(acc[mt][nt][hf * 2 + 0] + bv0, 0.f);
                    float v1 = fmaxf(acc[mt][nt][hf * 2 + 1] + bv1, 0.f);
                    *reinterpret_cast<__half2*>(sh + H1_OFF + r * H1_S + n0 + c) =
                        __floats2half2_rn(v0, v1);
                }
            }
    }

    // --- layer 2: h2 = relu(h1 @ W2 + b2)  [K=256, N=512] (overwrites X) ---
    for (int n0 = 0; n0 < 512; n0 += 128) {
        gemm_block(h1_u32, H1_S, w2, 512, n0, 8, ring_u32,
                   tid, wm, wn, a_r, a_k, b_k, b_n, acc);
#pragma unroll
        for (int mt = 0; mt < 2; ++mt)
#pragma unroll
            for (int nt = 0; nt < 4; ++nt) {
                int c = wn * 32 + nt * 8 + 2 * tig;
                float bv0 = b2[n0 + c], bv1 = b2[n0 + c + 1];
#pragma unroll
                for (int hf = 0; hf < 2; ++hf) {
                    int r = wm * 32 + mt * 16 + gid + hf * 8;
                    float v0 = fmaxf(acc[mt][nt][hf * 2 + 0] + bv0, 0.f);
                    float v1 = fmaxf(acc[mt][nt][hf * 2 + 1] + bv1, 0.f);
                    *reinterpret_cast<__half2*>(sh + H2_OFF + r * H2_S + n0 + c) =
                        __floats2half2_rn(v0, v1);
                }
            }
    }

    // --- layer 3: h = h2 @ W3 + b3         [K=512, N=128] -> gmem ---
    gemm_block(h2_u32, H2_S, w3, 128, 0, 16, ring_u32,
               tid, wm, wn, a_r, a_k, b_k, b_n, acc);
#pragma unroll
    for (int mt = 0; mt < 2; ++mt)
#pragma unroll
        for (int nt = 0; nt < 4; ++nt) {
            int c = wn * 32 + nt * 8 + 2 * tig;
            float bv0 = b3[c], bv1 = b3[c + 1];
#pragma unroll
            for (int hf = 0; hf < 2; ++hf) {
                int r  = wm * 32 + mt * 16 + gid + hf * 8;
                int gr = bm0 + r;
                if (gr < M) {
                    float v0 = acc[mt][nt][hf * 2 + 0] + bv0;
                    float v1 = acc[mt][nt][hf * 2 + 1] + bv1;
                    *reinterpret_cast<__half2*>(hh + (size_t)gr * 128 + c) =
                        __floats2half2_rn(v0, v1);
                    float* orow = out + (size_t)gr * 256;
                    orow[c    ] = v0;
                    orow[c + 1] = v1;
                }
            }
        }
}

// ---------------------------------------------------------------------------
// helpers
// ---------------------------------------------------------------------------
__global__ void f2h_kernel(const float* __restrict__ in, __half* __restrict__ out, int n) {
    int idx = (blockIdx.x * blockDim.x + threadIdx.x) * 4;
    if (idx < n) {
        float4 v = *reinterpret_cast<const float4*>(in + idx);
        __half2* o = reinterpret_cast<__half2*>(out + idx);
        o[0] = __floats2half2_rn(v.x, v.y);
        o[1] = __floats2half2_rn(v.z, v.w);
    }
}

__global__ void detect_kernel(const unsigned* __restrict__ w) {
    if (threadIdx.x == 0 && blockIdx.x == 0) {
        int ok = 1;
        for (int i = 1; i < 256; i += 2) ok &= (w[i] == 0u);
        g_is64 = ok;
    }
}

// ---------------------------------------------------------------------------
// CSR build: histogram -> chunked exclusive scan -> scatter
// ---------------------------------------------------------------------------
__global__ void hist_kernel(const void* __restrict__ dstp, int* __restrict__ counts, int E) {
    int i = blockIdx.x * blockDim.x + threadIdx.x;
    if (i >= E) return;
    atomicAdd(&counts[load_idx(dstp, i)], 1);
}

__global__ void chunk_reduce(const int* __restrict__ counts, int* __restrict__ bsum, int n) {
    __shared__ int sh[256];
    int base = blockIdx.x * CHUNK;
    int s = 0;
    for (int j = threadIdx.x; j < CHUNK; j += 256) {
        int idx = base + j;
        if (idx < n) s += counts[idx];
    }
    sh[threadIdx.x] = s;
    __syncthreads();
    for (int off = 128; off > 0; off >>= 1) {
        if (threadIdx.x < off) sh[threadIdx.x] += sh[threadIdx.x + off];
        __syncthreads();
    }
    if (threadIdx.x == 0) bsum[blockIdx.x] = sh[0];
}

__global__ void scan_partials(int* __restrict__ bsum, int nb) {
    __shared__ int sh[128];
    int t = threadIdx.x;
    int v = (t < nb) ? bsum[t] : 0;
    int orig = v;
#pragma unroll
    for (int off = 1; off < 128; off <<= 1) {
        sh[t] = v;
        __syncthreads();
        int add = (t >= off) ? sh[t - off] : 0;
        __syncthreads();
        v += add;
    }
    if (t < nb) bsum[t] = v - orig;
}

__global__ void chunk_scan(const int* __restrict__ counts, const int* __restrict__ bsum,
                           int* __restrict__ offsets, int n, int E) {
    __shared__ int sh[CHUNK];
    int t = threadIdx.x;
    int g = blockIdx.x * CHUNK + t;
    int v = (g < n) ? counts[g] : 0;
    int orig = v;
#pragma unroll
    for (int off = 1; off < CHUNK; off <<= 1) {
        sh[t] = v;
        __syncthreads();
        int add = (t >= off) ? sh[t - off] : 0;
        __syncthreads();
        v += add;
    }
    if (g < n) offsets[g] = v - orig + bsum[blockIdx.x];
    if (blockIdx.x == 0 && t == 0) offsets[n] = E;
}

__global__ void scatter_kernel(const void* __restrict__ srcp, const void* __restrict__ dstp,
                               int* __restrict__ cursor, int* __restrict__ perm, int E) {
    int i = blockIdx.x * blockDim.x + threadIdx.x;
    if (i >= E) return;
    int s = load_idx(srcp, i);
    int d = load_idx(dstp, i);
    int pos = atomicAdd(&cursor[d], 1);
    perm[pos] = s;
}

// ---------------------------------------------------------------------------
// Aggregation: one warp per dst node, fp32 register accumulation, no atomics.
// ---------------------------------------------------------------------------
__global__ void agg_kernel(const int* __restrict__ offsets, const int* __restrict__ perm,
                           const __half* __restrict__ hh, float* __restrict__ out, int M)
{
    int warp = (int)((blockIdx.x * (unsigned)blockDim.x + threadIdx.x) >> 5);
    int lane = threadIdx.x & 31;
    if (warp >= M) return;

    int e0 = offsets[warp];
    const int e1 = offsets[warp + 1];

    float a0 = 0.f, a1 = 0.f, a2 = 0.f, a3 = 0.f;

    while (e0 + 32 <= e1) {
        int idx = perm[e0 + lane];
#pragma unroll
        for (int j = 0; j < 32; ++j) {
            int s = __shfl_sync(0xffffffffu, idx, j);
            uint2 raw = *reinterpret_cast<const uint2*>(hh + (size_t)s * 128 + lane * 4);
            float2 f0 = __half22float2(*reinterpret_cast<__half2*>(&raw.x));
            float2 f1 = __half22float2(*reinterpret_cast<__half2*>(&raw.y));
            a0 += f0.x; a1 += f0.y; a2 += f1.x; a3 += f1.y;
        }
        e0 += 32;
    }
    int rem = e1 - e0;
    if (rem > 0) {
        int idx = (lane < rem) ? perm[e0 + lane] : 0;
        for (int j = 0; j < rem; ++j) {
            int s = __shfl_sync(0xffffffffu, idx, j);
            uint2 raw = *reinterpret_cast<const uint2*>(hh + (size_t)s * 128 + lane * 4);
            float2 f0 = __half22float2(*reinterpret_cast<__half2*>(&raw.x));
            float2 f1 = __half22float2(*reinterpret_cast<__half2*>(&raw.y));
            a0 += f0.x; a1 += f0.y; a2 += f1.x; a3 += f1.y;
        }
    }

    *reinterpret_cast<float4*>(out + (size_t)warp * 256 + 128 + lane * 4) =
        make_float4(a0, a1, a2, a3);
}

// ---------------------------------------------------------------------------
extern "C" void kernel_launch(void* const* d_in, const int* in_sizes, int n_in,
                              void* d_out, int out_size)
{
    const float* X   = (const float*)d_in[0];
    const void*  src = d_in[1];
    const void*  dst = d_in[2];
    const float* W1  = (const float*)d_in[3];
    const float* b1  = (const float*)d_in[4];
    const float* W2  = (const float*)d_in[5];
    const float* b2  = (const float*)d_in[6];
    const float* W3  = (const float*)d_in[7];
    const float* b3  = (const float*)d_in[8];
    float* out = (float*)d_out;

    const int N1 = in_sizes[4];          // 256
    const int N2 = in_sizes[6];          // 512
    const int N3 = in_sizes[8];          // 128
    const int K1 = in_sizes[3] / N1;     // 128
    const int M  = in_sizes[0] / K1;     // 100000
    const int E  = in_sizes[1];          // 3200000

    __half *hh, *w1, *w2, *w3;
    int *counts, *offsets, *cursor, *perm, *bsum;
    cudaGetSymbolAddress((void**)&hh, g_hh);
    cudaGetSymbolAddress((void**)&w1, g_w1);
    cudaGetSymbolAddress((void**)&w2, g_w2);
    cudaGetSymbolAddress((void**)&w3, g_w3);
    cudaGetSymbolAddress((void**)&counts,  g_counts);
    cudaGetSymbolAddress((void**)&offsets, g_offsets);
    cudaGetSymbolAddress((void**)&cursor,  g_cursor);
    cudaGetSymbolAddress((void**)&perm,    g_perm);
    cudaGetSymbolAddress((void**)&bsum,    g_bsum);

    cudaFuncSetAttribute(mlp_fused,
                         cudaFuncAttributeMaxDynamicSharedMemorySize, FUSED_SMEM);

    const int MT = (M + 127) / 128;
    const int nb = (M + CHUNK - 1) / CHUNK;
    const int EB = (E + 255) / 256;

    cudaStream_t s2;
    cudaEvent_t ev_fork, ev_w, ev_join;
    cudaStreamCreateWithFlags(&s2, cudaStreamNonBlocking);
    cudaEventCreateWithFlags(&ev_fork, cudaEventDisableTiming);
    cudaEventCreateWithFlags(&ev_w,    cudaEventDisableTiming);
    cudaEventCreateWithFlags(&ev_join, cudaEventDisableTiming);

    // fork
    cudaEventRecord(ev_fork, 0);
    cudaStreamWaitEvent(s2, ev_fork, 0);

    // side stream: weight conversions, then CSR build
    f2h_kernel<<<(K1 * N1 / 4 + 255) / 256, 256, 0, s2>>>(W1, w1, K1 * N1);
    f2h_kernel<<<(N1 * N2 / 4 + 255) / 256, 256, 0, s2>>>(W2, w2, N1 * N2);
    f2h_kernel<<<(N2 * N3 / 4 + 255) / 256, 256, 0, s2>>>(W3, w3, N2 * N3);
    cudaEventRecord(ev_w, s2);

    detect_kernel <<<1, 1, 0, s2>>>((const unsigned*)src);
    cudaMemsetAsync(counts, 0, (size_t)M * sizeof(int), s2);
    hist_kernel   <<<EB, 256, 0, s2>>>(dst, counts, E);
    chunk_reduce  <<<nb, 256, 0, s2>>>(counts, bsum, M);
    scan_partials <<<1, 128, 0, s2>>>(bsum, nb);
    chunk_scan    <<<nb, CHUNK, 0, s2>>>(counts, bsum, offsets, M, E);
    cudaMemcpyAsync(cursor, offsets, (size_t)M * sizeof(int),
                    cudaMemcpyDeviceToDevice, s2);
    scatter_kernel<<<EB, 256, 0, s2>>>(src, dst, cursor, perm, E);
    cudaEventRecord(ev_join, s2);

    // main: fused MLP (needs converted weights)
    cudaStreamWaitEvent(0, ev_w, 0);
    mlp_fused<<<MT, MLP_THREADS, FUSED_SMEM>>>(X, w1, b1, w2, b2, w3, b3, hh, out, M);

    // join: aggregation needs both the CSR and hh
    cudaStreamWaitEvent(0, ev_join, 0);
    agg_kernel<<<(M + 7) / 8, 256>>>(offsets, perm, hh, out, M);
}